// round 3
// baseline (speedup 1.0000x reference)
#include <cuda_runtime.h>
#include <cstdint>

// Per-row partial sums (B = 2048 for this problem; capacity with headroom).
static __device__ float g_rowsum[8192];

// -----------------------------------------------------------------------------
// Kernel 1: one block per row.
//   - streaming pass: loss*w sum (no mult), thread-local top-10 of x,
//     whitelist-presence flags p1/p2/p3
//   - block merge of top-10 (10 rounds of u64 max-reduce)
//   - correction for the <=10 top elements where (condA|condB)
// -----------------------------------------------------------------------------
__global__ void __launch_bounds__(256, 4)
asl_row_kernel(const float* __restrict__ X,
               const float* __restrict__ Y,
               const int*   __restrict__ cat,
               const unsigned char* __restrict__ inmap,
               int C)
{
    const int row = blockIdx.x;
    const int tid = threadIdx.x;
    const int lane = tid & 31;
    const int warp = tid >> 5;
    const unsigned FULL = 0xFFFFFFFFu;

    const float* __restrict__ xr = X + (size_t)row * C;
    const float* __restrict__ yr = Y + (size_t)row * C;

    // thread-local top-10, sorted descending; key = sortable(x) << 32 | (~idx)
    unsigned long long tk[10];
#pragma unroll
    for (int i = 0; i < 10; ++i) tk[i] = 0ULL;

    float sum = 0.0f;
    int flags = 0;

#pragma unroll 4
    for (int c = tid; c < C; c += 256) {
        const float xv = xr[c];
        const float yv = yr[c];

        // sortable-float key with lower-index tie-break
        unsigned ux = __float_as_uint(xv);
        ux ^= (ux & 0x80000000u) ? 0xFFFFFFFFu : 0x80000000u;
        const unsigned long long key =
            ((unsigned long long)ux << 32) | (unsigned long long)(0xFFFFFFFFu - (unsigned)c);
        if (key > tk[9]) {
            tk[9] = key;
#pragma unroll
            for (int j = 9; j > 0; --j) {
                unsigned long long a = tk[j - 1], b = tk[j];
                tk[j - 1] = a > b ? a : b;
                tk[j]     = a > b ? b : a;
            }
        }

        // loss * focal weight (y is exactly 0 or 1)
        const float sp = __fdividef(1.0f, 1.0f + __expf(-xv));
        const float sn = fminf(1.05f - sp, 1.0f);
        const bool  pos = (yv != 0.0f);
        const float pv  = pos ? sp : sn;
        const float l   = __logf(fmaxf(pv, 1e-8f));
        const float om  = 1.0f - pv;          // 1 - pt
        const float om2 = om * om;
        const float w   = pos ? om : om2 * om2;  // gamma = 1 (pos) / 4 (neg)
        sum += l * w;

        if (pos) {
            const int cv = __ldg(&cat[c]);
            flags |= (cv == 1) ? 1 : (cv == 2) ? 2 : (cv == 3) ? 4 : 0;
        }
    }

    __shared__ unsigned long long s_red[8];
    __shared__ unsigned long long s_win;
    __shared__ unsigned long long s_topk[10];
    __shared__ float s_sumw[8];
    __shared__ int s_flags;

    if (tid == 0) s_flags = 0;
    __syncthreads();

    // warp-level reductions of sum and flags
#pragma unroll
    for (int off = 16; off; off >>= 1) {
        sum   += __shfl_down_sync(FULL, sum, off);
        flags |= __shfl_down_sync(FULL, flags, off);
    }
    if (lane == 0) {
        s_sumw[warp] = sum;
        atomicOr(&s_flags, flags);
    }
    __syncthreads();

    // 10 rounds: block-wide max over each thread's current list head.
    int pos10 = 0;
    for (int k = 0; k < 10; ++k) {
        unsigned long long v = (pos10 < 10) ? tk[pos10] : 0ULL;
#pragma unroll
        for (int off = 16; off; off >>= 1) {
            unsigned long long o = __shfl_down_sync(FULL, v, off);
            if (o > v) v = o;
        }
        if (lane == 0) s_red[warp] = v;
        __syncthreads();
        if (warp == 0) {
            unsigned long long v2 = (lane < 8) ? s_red[lane] : 0ULL;
#pragma unroll
            for (int off = 4; off; off >>= 1) {
                unsigned long long o = __shfl_down_sync(FULL, v2, off);
                if (o > v2) v2 = o;
            }
            if (lane == 0) { s_win = v2; s_topk[k] = v2; }
        }
        __syncthreads();
        if (pos10 < 10 && tk[pos10] == s_win) ++pos10;   // keys unique (index field)
    }

    // correction for top-10 elements
    const int fl   = s_flags;
    const bool p1  = (fl & 1) != 0;
    const bool p2  = (fl & 2) != 0;
    const bool p3  = (fl & 4) != 0;
    const bool has4 = !(p1 | p2 | p3);

    float delta = 0.0f;
    if (tid < 10) {
        const unsigned idx = 0xFFFFFFFFu - (unsigned)(s_topk[tid] & 0xFFFFFFFFull);
        const float xv = xr[idx];
        const float yv = yr[idx];
        const float sp = __fdividef(1.0f, 1.0f + __expf(-xv));
        const float sn = fminf(1.05f - sp, 1.0f);
        const bool  pos = (yv != 0.0f);
        const float pv  = pos ? sp : sn;
        const float l   = __logf(fmaxf(pv, 1e-8f));
        const float om  = 1.0f - pv;
        const float om2 = om * om;
        const float w   = pos ? om : om2 * om2;

        const int  cv  = cat[idx];
        const bool inm = inmap[idx] != 0;
        const bool condA = (!inm) && has4;
        const bool condB = (cv == 1 && p1) || (cv == 2 && p2) ||
                           (cv == 3 && p3) || (cv == 4 && has4);
        if (condA || condB) {
            const float factor = (pos ? sn : sp) * 2.0f;   // ALPHA3 = 2
            delta = l * w * (factor - 1.0f);               // loss*w -> loss*w*factor
        }
    }
    if (warp == 0) {
#pragma unroll
        for (int off = 16; off; off >>= 1)
            delta += __shfl_down_sync(FULL, delta, off);
    }
    if (tid == 0) {
        float tot = delta;
#pragma unroll
        for (int i = 0; i < 8; ++i) tot += s_sumw[i];
        g_rowsum[row] = tot;
    }
}

// -----------------------------------------------------------------------------
// Kernel 2: deterministic double-precision reduction of row partials.
// -----------------------------------------------------------------------------
__global__ void asl_finalize_kernel(int B, float* __restrict__ out)
{
    __shared__ double s[256];
    double acc = 0.0;
    for (int i = threadIdx.x; i < B; i += 256)
        acc += (double)g_rowsum[i];
    s[threadIdx.x] = acc;
    __syncthreads();
#pragma unroll
    for (int off = 128; off; off >>= 1) {
        if (threadIdx.x < off) s[threadIdx.x] += s[threadIdx.x + off];
        __syncthreads();
    }
    if (threadIdx.x == 0) out[0] = -(float)s[0];
}

extern "C" void kernel_launch(void* const* d_in, const int* in_sizes, int n_in,
                              void* d_out, int out_size)
{
    const float*         X    = (const float*)d_in[0];
    const float*         Y    = (const float*)d_in[1];
    const int*           cat  = (const int*)d_in[2];
    const unsigned char* inm  = (const unsigned char*)d_in[3];

    const int C = in_sizes[2];            // 9605 (per-class arrays)
    const int B = in_sizes[0] / C;        // 2048

    asl_row_kernel<<<B, 256>>>(X, Y, cat, inm, C);
    asl_finalize_kernel<<<1, 256>>>(B, (float*)d_out);
}

// round 4
// speedup vs baseline: 1.7085x; 1.7085x over previous
#include <cuda_runtime.h>
#include <cstdint>

#define CAND 2048          // candidate buffer entries (u64)
#define TBL  2048          // bins per table
#define XSCALE 102.4f      // TBL / 20  (range [-10, 10])
#define XOFF   1024.0f     // 10 * XSCALE

static __device__ float g_rowsum[8192];
static __device__ float g_table[2 * TBL];   // [0..TBL) = f_neg, [TBL..2TBL) = f_pos
static __device__ int   g_count = 0;

// ---------------------------------------------------------------------------
// sortable-float key helpers
// ---------------------------------------------------------------------------
__device__ __forceinline__ unsigned sortkey32(float x) {
    unsigned u = __float_as_uint(x);
    return u ^ ((unsigned)(((int)u) >> 31) | 0x80000000u);
}
__device__ __forceinline__ unsigned long long makekey(unsigned k32, int c) {
    return ((unsigned long long)k32 << 32) |
           (unsigned long long)(0xFFFFFFFFu - (unsigned)c);
}

// ---------------------------------------------------------------------------
// Kernel 0: build the per-element loss tables once (exact math).
//   f_neg(x) = ln(max(min(1.05-sigmoid,1),eps)) * (1-pv)^4
//   f_pos(x) = ln(max(sigmoid,eps)) * (1-sigmoid)
// ---------------------------------------------------------------------------
__global__ void asl_build_table()
{
    int j = blockIdx.x * 256 + threadIdx.x;           // 0 .. 2*TBL-1
    bool pos = j >= TBL;
    int  q   = pos ? j - TBL : j;
    float x  = (q + 0.5f) * (20.0f / TBL) - 10.0f;    // bin center
    float sp = 1.0f / (1.0f + expf(-x));
    float v;
    if (pos) {
        v = logf(fmaxf(sp, 1e-8f)) * (1.0f - sp);
    } else {
        float pv = fminf(1.05f - sp, 1.0f);
        float om = 1.0f - pv;
        float om2 = om * om;
        v = logf(fmaxf(pv, 1e-8f)) * om2 * om2;
    }
    g_table[j] = v;
}

// ---------------------------------------------------------------------------
// per-element work: table lookup + whitelist flags
// ---------------------------------------------------------------------------
__device__ __forceinline__ void process_elem(float xv, float yv, int c,
                                             const int* __restrict__ cat,
                                             const float* __restrict__ s_tbl,
                                             float& sum, int& flags)
{
    bool pos = (yv != 0.0f);
    float fx = fmaf(xv, XSCALE, XOFF);
    int j = (int)fx;
    j = min(max(j, 0), TBL - 1);
    sum += s_tbl[j + (pos ? TBL : 0)];
    if (pos) {
        int cv = __ldg(&cat[c]);
        flags |= (1 << (cv - 1)) & 7;   // bits for cat 1/2/3; cat 4 -> 0
    }
}

// ---------------------------------------------------------------------------
// Kernel 1: one block per row. Threshold-prefilter top-10 + table-based sum.
// ---------------------------------------------------------------------------
__global__ void __launch_bounds__(256)
asl_row_kernel(const float* __restrict__ X,
               const float* __restrict__ Y,
               const int*   __restrict__ cat,
               const unsigned char* __restrict__ inmap,
               int C, int B, float* __restrict__ out)
{
    const int row  = blockIdx.x;
    const int tid  = threadIdx.x;
    const int lane = tid & 31;
    const int warp = tid >> 5;
    const unsigned FULL = 0xFFFFFFFFu;

    const float* __restrict__ xr = X + (size_t)row * C;
    const float* __restrict__ yr = Y + (size_t)row * C;

    __shared__ float s_tbl[2 * TBL];                  // 16 KB
    __shared__ unsigned long long s_buf[CAND];        // 16 KB
    __shared__ unsigned long long s_red[8];
    __shared__ unsigned long long s_win;
    __shared__ unsigned long long s_top[10];
    __shared__ float s_sumw[8];
    __shared__ int s_flags, s_cnt, s_last;

    // copy tables L2 -> smem (float4)
    {
        const float4* gt = (const float4*)g_table;
        float4* st = (float4*)s_tbl;
        for (int i = tid; i < (2 * TBL) / 4; i += 256) st[i] = gt[i];
    }
    if (tid == 0) { s_flags = 0; s_cnt = 10; }
    __syncthreads();

    float sum = 0.0f;
    int flags = 0;

    // ---- bootstrap: chunk 0 (elements 0..255): math + exact block top-10 ----
    unsigned long long mykey = 0ULL;
    if (tid < C) {
        float xv = xr[tid], yv = yr[tid];
        process_elem(xv, yv, tid, cat, s_tbl, sum, flags);
        mykey = makekey(sortkey32(xv), tid);
    }
    for (int k = 0; k < 10; ++k) {
        unsigned long long v = mykey;
#pragma unroll
        for (int off = 16; off; off >>= 1) {
            unsigned long long o = __shfl_down_sync(FULL, v, off);
            if (o > v) v = o;
        }
        if (lane == 0) s_red[warp] = v;
        __syncthreads();
        if (warp == 0) {
            unsigned long long v2 = (lane < 8) ? s_red[lane] : 0ULL;
#pragma unroll
            for (int off = 4; off; off >>= 1) {
                unsigned long long o = __shfl_down_sync(FULL, v2, off);
                if (o > v2) v2 = o;
            }
            if (lane == 0) { s_win = v2; s_buf[k] = v2; }
        }
        __syncthreads();
        if (mykey == s_win) mykey = 0ULL;
    }

    const unsigned long long thr = s_buf[9];
    const unsigned thr32 = (unsigned)(thr >> 32);

    // ---- main streaming loop: table sum + candidate collection ----
#pragma unroll 4
    for (int c = 256 + tid; c < C; c += 256) {
        float xv = xr[c], yv = yr[c];
        process_elem(xv, yv, c, cat, s_tbl, sum, flags);
        unsigned ux = sortkey32(xv);
        if (ux >= thr32) {
            unsigned long long key = makekey(ux, c);
            if (key > thr) {
                int p = atomicAdd(&s_cnt, 1);
                if (p < CAND) s_buf[p] = key;
            }
        }
    }

    // ---- reduce sum & flags ----
#pragma unroll
    for (int off = 16; off; off >>= 1) {
        sum   += __shfl_down_sync(FULL, sum, off);
        flags |= __shfl_down_sync(FULL, flags, off);
    }
    if (lane == 0) { s_sumw[warp] = sum; atomicOr(&s_flags, flags); }
    __syncthreads();

    // ---- extract exact block top-10 from candidate buffer ----
    for (;;) {
        int n = min(s_cnt, CAND);
        bool over = s_cnt > CAND;

        unsigned long long loc[8];
#pragma unroll
        for (int t = 0; t < 8; ++t) {
            int i = tid + (t << 8);
            loc[t] = (i < n) ? s_buf[i] : 0ULL;
        }
        for (int k = 0; k < 10; ++k) {
            unsigned long long v = 0ULL;
#pragma unroll
            for (int t = 0; t < 8; ++t) if (loc[t] > v) v = loc[t];
#pragma unroll
            for (int off = 16; off; off >>= 1) {
                unsigned long long o = __shfl_down_sync(FULL, v, off);
                if (o > v) v = o;
            }
            if (lane == 0) s_red[warp] = v;
            __syncthreads();
            if (warp == 0) {
                unsigned long long v2 = (lane < 8) ? s_red[lane] : 0ULL;
#pragma unroll
                for (int off = 4; off; off >>= 1) {
                    unsigned long long o = __shfl_down_sync(FULL, v2, off);
                    if (o > v2) v2 = o;
                }
                if (lane == 0) { s_win = v2; s_top[k] = v2; }
            }
            __syncthreads();
#pragma unroll
            for (int t = 0; t < 8; ++t) if (loc[t] == s_win) loc[t] = 0ULL;
        }
        if (!over) break;

        // fallback (effectively unreachable for this data): raise threshold,
        // recollect all elements with key >= new threshold. Terminates since
        // the threshold strictly increases each pass.
        __syncthreads();
        if (tid == 0) s_cnt = 0;
        unsigned long long th2 = s_top[9];
        unsigned th2h = (unsigned)(th2 >> 32);
        __syncthreads();
        for (int c = tid; c < C; c += 256) {
            unsigned ux = sortkey32(xr[c]);
            if (ux >= th2h) {
                unsigned long long key = makekey(ux, c);
                if (key >= th2) {
                    int p = atomicAdd(&s_cnt, 1);
                    if (p < CAND) s_buf[p] = key;
                }
            }
        }
        __syncthreads();
    }

    // ---- correction for the top-10 elements (exact math) ----
    const int fl = s_flags;
    const bool p1 = (fl & 1) != 0, p2 = (fl & 2) != 0, p3 = (fl & 4) != 0;
    const bool has4 = !(p1 | p2 | p3);

    float delta = 0.0f;
    if (tid < 10) {
        const unsigned idx = 0xFFFFFFFFu - (unsigned)(s_top[tid] & 0xFFFFFFFFull);
        const float xv = xr[idx];
        const float yv = yr[idx];
        const float sp = __fdividef(1.0f, 1.0f + __expf(-xv));
        const float sn = fminf(1.05f - sp, 1.0f);
        const bool  pos = (yv != 0.0f);
        const float pv  = pos ? sp : sn;
        const float l   = __logf(fmaxf(pv, 1e-8f));
        const float om  = 1.0f - pv;
        const float om2 = om * om;
        const float w   = pos ? om : om2 * om2;

        const int  cv  = cat[idx];
        const bool inm = inmap[idx] != 0;
        const bool condA = (!inm) && has4;
        const bool condB = (cv == 1 && p1) || (cv == 2 && p2) ||
                           (cv == 3 && p3) || (cv == 4 && has4);
        if (condA || condB) {
            const float factor = (pos ? sn : sp) * 2.0f;  // ALPHA3 = 2
            delta = l * w * (factor - 1.0f);
        }
    }
    if (warp == 0) {
#pragma unroll
        for (int off = 16; off; off >>= 1)
            delta += __shfl_down_sync(FULL, delta, off);
    }
    if (tid == 0) {
        float tot = delta;
#pragma unroll
        for (int i = 0; i < 8; ++i) tot += s_sumw[i];
        g_rowsum[row] = tot;
    }

    // ---- last-block finalize: deterministic double reduction ----
    __threadfence();
    if (tid == 0) s_last = (atomicAdd(&g_count, 1) == gridDim.x - 1) ? 1 : 0;
    __syncthreads();
    if (s_last) {
        __threadfence();
        double* sd = (double*)s_buf;
        double acc = 0.0;
        for (int i = tid; i < B; i += 256) acc += (double)g_rowsum[i];
        sd[tid] = acc;
        __syncthreads();
#pragma unroll
        for (int off = 128; off; off >>= 1) {
            if (tid < off) sd[tid] += sd[tid + off];
            __syncthreads();
        }
        if (tid == 0) { out[0] = -(float)sd[0]; g_count = 0; }
    }
}

extern "C" void kernel_launch(void* const* d_in, const int* in_sizes, int n_in,
                              void* d_out, int out_size)
{
    const float*         X   = (const float*)d_in[0];
    const float*         Y   = (const float*)d_in[1];
    const int*           cat = (const int*)d_in[2];
    const unsigned char* inm = (const unsigned char*)d_in[3];

    const int C = in_sizes[2];        // per-class arrays -> 9605
    const int B = in_sizes[0] / C;    // 2048

    asl_build_table<<<(2 * TBL) / 256, 256>>>();
    asl_row_kernel<<<B, 256>>>(X, Y, cat, inm, C, B, (float*)d_out);
}